// round 9
// baseline (speedup 1.0000x reference)
#include <cuda_runtime.h>
#include <cuda_bf16.h>

#define B_      4
#define CIN     256
#define HH      32
#define WW      88
#define HW      2816
#define PTOT    11264
#define COUT    128
#define OUTH    432
#define OUTW    496
#define XVEC    124             // 496/4
#define NPLANE  512
#define YTILE   54              // 432 = 8*54
#define NYT     8
#define SROWS   6
#define YHALF   27

#define KC      16              // GEMM k-chunk
#define PB      64              // positions per block
#define CB      64              // channels per block

__device__ float g_ctx[NPLANE * HW];
__device__ float g_WcT[CIN * COUT];   // [k][c], pre-scaled by 1/64

// ---------------------------------------------------------------------------
// packed f32x2 helpers
// ---------------------------------------------------------------------------
__device__ __forceinline__ unsigned long long pk2(float x) {
    unsigned long long r;
    asm("mov.b64 %0, {%1, %1};" : "=l"(r) : "f"(x));
    return r;
}
__device__ __forceinline__ void ffma2(unsigned long long& d,
                                      unsigned long long a,
                                      unsigned long long b) {
    asm("fma.rn.f32x2 %0, %1, %2, %0;" : "+l"(d) : "l"(a), "l"(b));
}
__device__ __forceinline__ float2 upk(unsigned long long v) {
    float2 r;
    asm("mov.b64 {%0, %1}, %2;" : "=f"(r.x), "=f"(r.y) : "l"(v));
    return r;
}

// ---------------------------------------------------------------------------
// Kernel 0: coalesced tile-transpose prep: WcT[k][c] = Wc[64+c][k] / 64
// 32x32 tiles via smem; both global sides coalesced.
// ---------------------------------------------------------------------------
__global__ __launch_bounds__(256)
void lss_prep_kernel(const float* __restrict__ Wc)
{
    __shared__ float s[32][33];
    const int tx = threadIdx.x & 31;
    const int ty = threadIdx.x >> 5;      // 0..7
    const int k0 = blockIdx.x * 32;       // 8 k-tiles
    const int c0 = blockIdx.y * 32;       // 4 c-tiles

#pragma unroll
    for (int j = 0; j < 4; j++) {
        int c = c0 + ty + 8 * j;
        s[ty + 8 * j][tx] = Wc[(64 + c) * CIN + k0 + tx] * (1.0f / 64.0f);
    }
    __syncthreads();
#pragma unroll
    for (int j = 0; j < 4; j++) {
        int k = k0 + ty + 8 * j;
        g_WcT[k * COUT + c0 + tx] = s[tx][ty + 8 * j];
    }
}

// ---------------------------------------------------------------------------
// Kernel 1: GEMM v3. 64-thread blocks, block tile 64c x 64p,
// thread tile 4 channel-pairs x 8 positions (FFMA2). KC=16 double-buffered.
// Per warp-k: 4 LDS.128 + 32 FFMA2 -> LDS and FMA pipes balanced.
// ---------------------------------------------------------------------------
__global__ __launch_bounds__(64)
void lss_gemm_kernel(const float* __restrict__ feat,
                     const float* __restrict__ bc)
{
    __shared__ float Ws[2][KC * CB];   // 8KB
    __shared__ float Fs[2][KC * PB];   // 8KB

    const int tid   = threadIdx.x;
    const int p0    = blockIdx.x * PB;
    const int b     = p0 / HW;
    const int hw0   = p0 - b * HW;
    const int cbase = blockIdx.y * CB;          // 0 or 64

    const float4* WcT4  = (const float4*)g_WcT;                            // row stride 32 f4
    const float4* feat4 = (const float4*)(feat + (size_t)b * CIN * HW + hw0); // row stride 704 f4

    const int lkk = tid >> 4;        // 0..3
    const int lcv = tid & 15;        // 0..15

    float4 wreg[4], freg[4];

    // prologue: chunk 0
#pragma unroll
    for (int it = 0; it < 4; it++) {
        int kk = lkk + it * 4;
        wreg[it] = WcT4[(size_t)kk * 32 + (cbase >> 2) + lcv];
        freg[it] = feat4[(size_t)kk * 704 + lcv];
    }
#pragma unroll
    for (int it = 0; it < 4; it++) {
        int kk = lkk + it * 4;
        ((float4*)Ws[0])[kk * 16 + lcv] = wreg[it];
        ((float4*)Fs[0])[kk * 16 + lcv] = freg[it];
    }
    __syncthreads();

    const int cy = (tid >> 3) << 3;   // channel base 0..56 (4 pairs)
    const int px = (tid & 7) << 3;    // position base 0..56 (8 pos)

    unsigned long long acc[4][8];     // [cpair][pos]
#pragma unroll
    for (int i = 0; i < 4; i++)
#pragma unroll
        for (int j = 0; j < 8; j++) acc[i][j] = 0ull;

    int buf = 0;
    for (int ch = 0; ch < CIN / KC; ch++) {
        if (ch < CIN / KC - 1) {
            int k0 = (ch + 1) * KC;
#pragma unroll
            for (int it = 0; it < 4; it++) {
                int kk = k0 + lkk + it * 4;
                wreg[it] = WcT4[(size_t)kk * 32 + (cbase >> 2) + lcv];
                freg[it] = feat4[(size_t)kk * 704 + lcv];
            }
        }

        const float* Wsb = Ws[buf] + cy;
        const float* Fsb = Fs[buf] + px;
#pragma unroll
        for (int k = 0; k < KC; k++) {
            ulonglong2 w01 = *(const ulonglong2*)(Wsb + k * CB);       // pairs 0,1
            ulonglong2 w23 = *(const ulonglong2*)(Wsb + k * CB + 4);   // pairs 2,3
            float4 fa = *(const float4*)(Fsb + k * PB);
            float4 fb = *(const float4*)(Fsb + k * PB + 4);
            unsigned long long f0 = pk2(fa.x), f1 = pk2(fa.y),
                               f2 = pk2(fa.z), f3 = pk2(fa.w),
                               f4_ = pk2(fb.x), f5 = pk2(fb.y),
                               f6 = pk2(fb.z), f7 = pk2(fb.w);
            ffma2(acc[0][0], w01.x, f0); ffma2(acc[0][1], w01.x, f1);
            ffma2(acc[0][2], w01.x, f2); ffma2(acc[0][3], w01.x, f3);
            ffma2(acc[0][4], w01.x, f4_); ffma2(acc[0][5], w01.x, f5);
            ffma2(acc[0][6], w01.x, f6); ffma2(acc[0][7], w01.x, f7);
            ffma2(acc[1][0], w01.y, f0); ffma2(acc[1][1], w01.y, f1);
            ffma2(acc[1][2], w01.y, f2); ffma2(acc[1][3], w01.y, f3);
            ffma2(acc[1][4], w01.y, f4_); ffma2(acc[1][5], w01.y, f5);
            ffma2(acc[1][6], w01.y, f6); ffma2(acc[1][7], w01.y, f7);
            ffma2(acc[2][0], w23.x, f0); ffma2(acc[2][1], w23.x, f1);
            ffma2(acc[2][2], w23.x, f2); ffma2(acc[2][3], w23.x, f3);
            ffma2(acc[2][4], w23.x, f4_); ffma2(acc[2][5], w23.x, f5);
            ffma2(acc[2][6], w23.x, f6); ffma2(acc[2][7], w23.x, f7);
            ffma2(acc[3][0], w23.y, f0); ffma2(acc[3][1], w23.y, f1);
            ffma2(acc[3][2], w23.y, f2); ffma2(acc[3][3], w23.y, f3);
            ffma2(acc[3][4], w23.y, f4_); ffma2(acc[3][5], w23.y, f5);
            ffma2(acc[3][6], w23.y, f6); ffma2(acc[3][7], w23.y, f7);
        }

        if (ch < CIN / KC - 1) {
            int nb = buf ^ 1;
#pragma unroll
            for (int it = 0; it < 4; it++) {
                int kk = lkk + it * 4;
                ((float4*)Ws[nb])[kk * 16 + lcv] = wreg[it];
                ((float4*)Fs[nb])[kk * 16 + lcv] = freg[it];
            }
            __syncthreads();
            buf = nb;
        }
    }

    const float inv64 = 1.0f / 64.0f;
#pragma unroll
    for (int i = 0; i < 4; i++) {
        int c0 = cbase + cy + 2 * i;
        float b0 = bc[64 + c0] * inv64;
        float b1 = bc[64 + c0 + 1] * inv64;
        float2 v[8];
#pragma unroll
        for (int j = 0; j < 8; j++) v[j] = upk(acc[i][j]);
        float* d0 = &g_ctx[((size_t)(b * COUT + c0)) * HW + hw0 + px];
        float* d1 = &g_ctx[((size_t)(b * COUT + c0 + 1)) * HW + hw0 + px];
        *(float4*)d0       = make_float4(v[0].x + b0, v[1].x + b0, v[2].x + b0, v[3].x + b0);
        *(float4*)(d0 + 4) = make_float4(v[4].x + b0, v[5].x + b0, v[6].x + b0, v[7].x + b0);
        *(float4*)d1       = make_float4(v[0].y + b1, v[1].y + b1, v[2].y + b1, v[3].y + b1);
        *(float4*)(d1 + 4) = make_float4(v[4].y + b1, v[5].y + b1, v[6].y + b1, v[7].y + b1);
    }
}

// ---------------------------------------------------------------------------
// Kernel 2: separable bilinear upsample (R7 proven version, unchanged).
// ---------------------------------------------------------------------------
__global__ __launch_bounds__(256)
void lss_upsample_kernel(float* __restrict__ out)
{
    __shared__ float raw[SROWS][WW];
    __shared__ float hrow[SROWS][OUTW];
    __shared__ float ywy[YTILE];
    __shared__ int   yi0s[YTILE];

    const int tid   = threadIdx.x;
    const int t     = blockIdx.x;      // 0..7
    const int plane = blockIdx.y;      // 0..511

    const float SY = 32.0f / 432.0f;
    const float OY = 16.0f / 432.0f - 0.5f;
    const float SX = 88.0f / 496.0f;
    const float OX = 44.0f / 496.0f - 0.5f;

    const int rbase = max(4 * t - 1, 0);

    if (tid < YTILE) {
        int Y = t * YTILE + tid;
        float fy = fminf(fmaxf((float)Y * SY + OY, 0.0f), 31.0f);
        int   y0 = (int)fy;
        ywy[tid]  = fy - (float)y0;
        yi0s[tid] = y0 - rbase;        // 0..4, monotone non-decreasing
    }

    // Phase A: load 6 source rows (edge-clamped)
    const float* cb = g_ctx + (size_t)plane * HW;
    for (int i = tid; i < SROWS * WW; i += 256) {
        int r = i / WW, x = i - r * WW;
        int ry = min(rbase + r, HH - 1);
        raw[r][x] = cb[ry * WW + x];
    }
    __syncthreads();

    // Phase B: horizontal interpolation
    for (int i = tid; i < SROWS * 512; i += 256) {
        int r = i >> 9, X = i & 511;
        if (X < OUTW) {
            float fx = fminf(fmaxf((float)X * SX + OX, 0.0f), 87.0f);
            int   x0 = (int)fx;
            float wx = fx - (float)x0;
            int   x1 = min(x0 + 1, WW - 1);
            float a = raw[r][x0];
            hrow[r][X] = fmaf(wx, raw[r][x1] - a, a);
        }
    }
    __syncthreads();

    // Phase C: vertical pass. Two 124-thread halves each cover 27 rows.
    const int half = tid >> 7;         // 0 or 1
    const int lx   = tid & 127;        // x-column within half
    if (lx < XVEC) {
        const int xo    = lx << 2;
        const int ybeg  = half * YHALF;
        const int yend  = ybeg + YHALF;
        float4* orow = (float4*)out + (size_t)plane * OUTH * XVEC
                       + (size_t)(t * YTILE + ybeg) * XVEC + lx;
        int yy = ybeg;
        const int r0 = yi0s[ybeg];
#pragma unroll
        for (int r = 0; r < 5; r++) {
            if (r >= r0 && yy < yend && yi0s[yy] == r) {
                float4 a = *(const float4*)&hrow[r][xo];
                float4 b = *(const float4*)&hrow[r + 1][xo];
                float4 d;
                d.x = b.x - a.x; d.y = b.y - a.y; d.z = b.z - a.z; d.w = b.w - a.w;
                do {
                    float wy = ywy[yy];
                    float4 o;
                    o.x = fmaf(wy, d.x, a.x);
                    o.y = fmaf(wy, d.y, a.y);
                    o.z = fmaf(wy, d.z, a.z);
                    o.w = fmaf(wy, d.w, a.w);
                    __stcs(orow, o);
                    orow += XVEC;
                    yy++;
                } while (yy < yend && yi0s[yy] == r);
            }
        }
    }
}

extern "C" void kernel_launch(void* const* d_in, const int* in_sizes, int n_in,
                              void* d_out, int out_size)
{
    const float* feat = (const float*)d_in[0];
    const float* Wc   = (const float*)d_in[1];
    const float* bc   = (const float*)d_in[2];
    float* out        = (float*)d_out;

    dim3 pgrid(CIN / 32, COUT / 32);
    lss_prep_kernel<<<pgrid, 256>>>(Wc);

    dim3 ggrid(PTOT / PB, 2);
    lss_gemm_kernel<<<ggrid, 64>>>(feat, bc);

    dim3 ugrid(NYT, NPLANE);
    lss_upsample_kernel<<<ugrid, 256>>>(out);
}